// round 2
// baseline (speedup 1.0000x reference)
#include <cuda_runtime.h>
#include <math.h>

// Problem constants (fixed by the reference).
#define SQ   4096      // sequence length
#define DIM  2048      // model dim
#define HD   128       // head dim
#define NH   16        // query heads
#define NKV  4         // kv heads
#define KVD  (NKV*HD)  // 512

// Scratch (device globals; allocation inside kernel_launch is forbidden).
__device__ float g_q[(size_t)SQ * DIM];          // 32 MB
__device__ float g_k[(size_t)SQ * KVD];          // 8 MB
__device__ float g_v[(size_t)SQ * KVD];          // 8 MB
__device__ float g_sc[(size_t)NH * SQ * SQ];     // 1 GiB scores/probs
__device__ float g_attn[(size_t)SQ * DIM];       // 32 MB

// ---------------------------------------------------------------------------
// Generic fp32 SGEMM, C = A*B, 128x128 tile, BK=8, 256 threads, 8x8/thread.
// All dims assumed multiples of the tile factors (true for every call here).
// ---------------------------------------------------------------------------
__global__ __launch_bounds__(256) void sgemm_nn(
    const float* __restrict__ A, const float* __restrict__ B, float* __restrict__ C,
    int M, int N, int K, int lda, int ldb, int ldc)
{
    __shared__ float As[8][128];
    __shared__ float Bs[8][128];
    const int tid = threadIdx.x;
    const int m0 = blockIdx.y * 128;
    const int n0 = blockIdx.x * 128;

    const int aRow = tid >> 1;            // 0..127
    const int aCol = (tid & 1) * 4;       // 0 or 4
    const int bRow = tid >> 5;            // 0..7
    const int bCol = (tid & 31) * 4;      // 0..124
    const int tr = (tid >> 4) * 8;
    const int tc = (tid & 15) * 8;

    float acc[8][8];
    #pragma unroll
    for (int i = 0; i < 8; i++)
        #pragma unroll
        for (int j = 0; j < 8; j++) acc[i][j] = 0.f;

    for (int k0 = 0; k0 < K; k0 += 8) {
        float4 a = *(const float4*)&A[(size_t)(m0 + aRow) * lda + k0 + aCol];
        As[aCol + 0][aRow] = a.x;
        As[aCol + 1][aRow] = a.y;
        As[aCol + 2][aRow] = a.z;
        As[aCol + 3][aRow] = a.w;
        float4 b = *(const float4*)&B[(size_t)(k0 + bRow) * ldb + n0 + bCol];
        *(float4*)&Bs[bRow][bCol] = b;
        __syncthreads();
        #pragma unroll
        for (int k = 0; k < 8; k++) {
            float rm[8], rn[8];
            #pragma unroll
            for (int i = 0; i < 8; i++) rm[i] = As[k][tr + i];
            #pragma unroll
            for (int j = 0; j < 8; j++) rn[j] = Bs[k][tc + j];
            #pragma unroll
            for (int i = 0; i < 8; i++)
                #pragma unroll
                for (int j = 0; j < 8; j++)
                    acc[i][j] += rm[i] * rn[j];
        }
        __syncthreads();
    }
    #pragma unroll
    for (int i = 0; i < 8; i++)
        #pragma unroll
        for (int j = 0; j < 8; j += 4)
            *(float4*)&C[(size_t)(m0 + tr + i) * ldc + n0 + tc + j] =
                make_float4(acc[i][j], acc[i][j+1], acc[i][j+2], acc[i][j+3]);
}

// ---------------------------------------------------------------------------
// RoPE (interleaved pairs), applied in place to Q or K.
// ---------------------------------------------------------------------------
__global__ void rope_kernel(float* __restrict__ t,
                            const float* __restrict__ cosT,
                            const float* __restrict__ sinT,
                            int nheads, int ld)
{
    int i = blockIdx.x * blockDim.x + threadIdx.x;
    int total = SQ * nheads * (HD / 2);
    if (i >= total) return;
    int p = i & 63;               // pair index 0..63
    int rest = i >> 6;
    int h = rest % nheads;
    int s = rest / nheads;
    float c  = cosT[s * 64 + p];
    float sn = sinT[s * 64 + p];
    float* base = t + (size_t)s * ld + h * HD + 2 * p;
    float x1 = base[0], x2 = base[1];
    base[0] = x1 * c - x2 * sn;
    base[1] = x1 * sn + x2 * c;
}

// ---------------------------------------------------------------------------
// Scores: S[h, s, t] = Q[s, h, :] . K[t, h/4, :]   (NT GEMM, K-dim = 128)
// Causal block skip: block (bx,by) dead iff bx > by. blockIdx.z = head.
// ---------------------------------------------------------------------------
__global__ __launch_bounds__(256) void qk_kernel()
{
    const int h = blockIdx.z;
    if (blockIdx.x > blockIdx.y) return;   // fully-masked tile
    const float* A = g_q + h * HD;               // lda = DIM
    const float* B = g_k + (h >> 2) * HD;        // ldb = KVD, accessed transposed
    float* C = g_sc + (size_t)h * SQ * SQ;       // ldc = SQ

    __shared__ float As[8][128];
    __shared__ float Bs[8][128];
    const int tid = threadIdx.x;
    const int m0 = blockIdx.y * 128;
    const int n0 = blockIdx.x * 128;

    const int aRow = tid >> 1;
    const int aCol = (tid & 1) * 4;
    const int tr = (tid >> 4) * 8;
    const int tc = (tid & 15) * 8;

    float acc[8][8];
    #pragma unroll
    for (int i = 0; i < 8; i++)
        #pragma unroll
        for (int j = 0; j < 8; j++) acc[i][j] = 0.f;

    for (int k0 = 0; k0 < HD; k0 += 8) {
        float4 a = *(const float4*)&A[(size_t)(m0 + aRow) * DIM + k0 + aCol];
        As[aCol + 0][aRow] = a.x;
        As[aCol + 1][aRow] = a.y;
        As[aCol + 2][aRow] = a.z;
        As[aCol + 3][aRow] = a.w;
        // B transposed load: rows are t (n), cols are k
        float4 b = *(const float4*)&B[(size_t)(n0 + aRow) * KVD + k0 + aCol];
        Bs[aCol + 0][aRow] = b.x;
        Bs[aCol + 1][aRow] = b.y;
        Bs[aCol + 2][aRow] = b.z;
        Bs[aCol + 3][aRow] = b.w;
        __syncthreads();
        #pragma unroll
        for (int k = 0; k < 8; k++) {
            float rm[8], rn[8];
            #pragma unroll
            for (int i = 0; i < 8; i++) rm[i] = As[k][tr + i];
            #pragma unroll
            for (int j = 0; j < 8; j++) rn[j] = Bs[k][tc + j];
            #pragma unroll
            for (int i = 0; i < 8; i++)
                #pragma unroll
                for (int j = 0; j < 8; j++)
                    acc[i][j] += rm[i] * rn[j];
        }
        __syncthreads();
    }
    #pragma unroll
    for (int i = 0; i < 8; i++)
        #pragma unroll
        for (int j = 0; j < 8; j += 4)
            *(float4*)&C[(size_t)(m0 + tr + i) * SQ + n0 + tc + j] =
                make_float4(acc[i][j], acc[i][j+1], acc[i][j+2], acc[i][j+3]);
}

// ---------------------------------------------------------------------------
// Row softmax with scale + causal truncation. Writes zeros beyond t = s.
// grid = (SQ, NH), 256 threads.
// ---------------------------------------------------------------------------
__global__ __launch_bounds__(256) void softmax_kernel()
{
    const int s = blockIdx.x;
    const int h = blockIdx.y;
    float* row = g_sc + ((size_t)h * SQ + s) * SQ;
    const int L = s + 1;
    const float scale = 0.08838834764831845f;  // 1/sqrt(128)
    __shared__ float red[256];
    const int t0 = threadIdx.x;

    float m = -1e30f;
    for (int t = t0; t < L; t += 256) m = fmaxf(m, row[t]);
    red[t0] = m;
    __syncthreads();
    for (int o = 128; o > 0; o >>= 1) {
        if (t0 < o) red[t0] = fmaxf(red[t0], red[t0 + o]);
        __syncthreads();
    }
    m = red[0] * scale;   // max of scaled values (scale > 0)
    __syncthreads();

    float sum = 0.f;
    for (int t = t0; t < L; t += 256) {
        float e = __expf(row[t] * scale - m);
        row[t] = e;
        sum += e;
    }
    red[t0] = sum;
    __syncthreads();
    for (int o = 128; o > 0; o >>= 1) {
        if (t0 < o) red[t0] += red[t0 + o];
        __syncthreads();
    }
    const float inv = 1.f / red[0];

    for (int t = t0; t < L; t += 256) row[t] *= inv;
    for (int t = L + t0; t < SQ; t += 256) row[t] = 0.f;
}

// ---------------------------------------------------------------------------
// PV: attn[s, h*128 + d] = sum_t P[h, s, t] * V[t, h/4, d]. blockIdx.z = head.
// N = 128 (one block column), K = 4096.
// ---------------------------------------------------------------------------
__global__ __launch_bounds__(256) void pv_kernel()
{
    const int h = blockIdx.z;
    const float* A = g_sc + (size_t)h * SQ * SQ;   // lda = SQ
    const float* B = g_v + (h >> 2) * HD;          // ldb = KVD
    float* C = g_attn + h * HD;                    // ldc = DIM

    __shared__ float As[8][128];
    __shared__ float Bs[8][128];
    const int tid = threadIdx.x;
    const int m0 = blockIdx.y * 128;

    const int aRow = tid >> 1;
    const int aCol = (tid & 1) * 4;
    const int bRow = tid >> 5;
    const int bCol = (tid & 31) * 4;
    const int tr = (tid >> 4) * 8;
    const int tc = (tid & 15) * 8;

    float acc[8][8];
    #pragma unroll
    for (int i = 0; i < 8; i++)
        #pragma unroll
        for (int j = 0; j < 8; j++) acc[i][j] = 0.f;

    // Causal: P[s, t] = 0 for t > s; rows in this block have s <= m0+127,
    // so k-range beyond m0+128 contributes nothing.
    const int Keff = m0 + 128;
    for (int k0 = 0; k0 < Keff; k0 += 8) {
        float4 a = *(const float4*)&A[(size_t)(m0 + aRow) * SQ + k0 + aCol];
        As[aCol + 0][aRow] = a.x;
        As[aCol + 1][aRow] = a.y;
        As[aCol + 2][aRow] = a.z;
        As[aCol + 3][aRow] = a.w;
        float4 b = *(const float4*)&B[(size_t)(k0 + bRow) * KVD + bCol];
        *(float4*)&Bs[bRow][bCol] = b;
        __syncthreads();
        #pragma unroll
        for (int k = 0; k < 8; k++) {
            float rm[8], rn[8];
            #pragma unroll
            for (int i = 0; i < 8; i++) rm[i] = As[k][tr + i];
            #pragma unroll
            for (int j = 0; j < 8; j++) rn[j] = Bs[k][tc + j];
            #pragma unroll
            for (int i = 0; i < 8; i++)
                #pragma unroll
                for (int j = 0; j < 8; j++)
                    acc[i][j] += rm[i] * rn[j];
        }
        __syncthreads();
    }
    #pragma unroll
    for (int i = 0; i < 8; i++)
        #pragma unroll
        for (int j = 0; j < 8; j += 4)
            *(float4*)&C[(size_t)(m0 + tr + i) * DIM + tc + j] =
                make_float4(acc[i][j], acc[i][j+1], acc[i][j+2], acc[i][j+3]);
}

// ---------------------------------------------------------------------------
// kernel_launch
// Inputs: 0:x 1:start_pos 2:freqs_cos 3:freqs_sin 4:mask 5:wq 6:wk 7:wv 8:wo
// ---------------------------------------------------------------------------
extern "C" void kernel_launch(void* const* d_in, const int* in_sizes, int n_in,
                              void* d_out, int out_size)
{
    const float* x    = (const float*)d_in[0];
    const float* fcos = (const float*)d_in[2];
    const float* fsin = (const float*)d_in[3];
    const float* wq   = (const float*)d_in[5];
    const float* wk   = (const float*)d_in[6];
    const float* wv   = (const float*)d_in[7];
    const float* wo   = (const float*)d_in[8];
    float* out = (float*)d_out;

    float* q; cudaGetSymbolAddress((void**)&q, g_q);
    float* k; cudaGetSymbolAddress((void**)&k, g_k);
    float* v; cudaGetSymbolAddress((void**)&v, g_v);
    float* at; cudaGetSymbolAddress((void**)&at, g_attn);

    // QKV projections
    sgemm_nn<<<dim3(DIM / 128, SQ / 128), 256>>>(x, wq, q, SQ, DIM, DIM, DIM, DIM, DIM);
    sgemm_nn<<<dim3(KVD / 128, SQ / 128), 256>>>(x, wk, k, SQ, KVD, DIM, DIM, KVD, KVD);
    sgemm_nn<<<dim3(KVD / 128, SQ / 128), 256>>>(x, wv, v, SQ, KVD, DIM, DIM, KVD, KVD);

    // RoPE on Q and K
    {
        int totQ = SQ * NH * (HD / 2);
        rope_kernel<<<(totQ + 255) / 256, 256>>>(q, fcos, fsin, NH, DIM);
        int totK = SQ * NKV * (HD / 2);
        rope_kernel<<<(totK + 255) / 256, 256>>>(k, fcos, fsin, NKV, KVD);
    }

    // Scores (causal-skipped), softmax, PV
    qk_kernel<<<dim3(SQ / 128, SQ / 128, NH), 256>>>();
    softmax_kernel<<<dim3(SQ, NH), 256>>>();
    pv_kernel<<<dim3(1, SQ / 128, NH), 256>>>();

    // Output projection
    sgemm_nn<<<dim3(DIM / 128, SQ / 128), 256>>>(at, wo, out, SQ, DIM, DIM, DIM, DIM, DIM);
}

// round 5
// speedup vs baseline: 2.6805x; 2.6805x over previous
#include <cuda_runtime.h>
#include <cuda_bf16.h>
#include <cstdint>
#include <math.h>

#define SQ   4096
#define DIM  2048
#define HD   128
#define NH   16
#define NKV  4
#define KVD  512

// ---------------- device scratch ----------------
__device__ float g_q[(size_t)SQ * DIM];
__device__ float g_k[(size_t)SQ * KVD];
__device__ float g_v[(size_t)SQ * KVD];
__device__ float g_sc[(size_t)NH * SQ * SQ];      // fp32 scores (1 GiB)
__device__ float g_attn[(size_t)SQ * DIM];

__device__ __nv_bfloat16 g_xh[(size_t)SQ * DIM],  g_xl[(size_t)SQ * DIM];
__device__ __nv_bfloat16 g_qh[(size_t)SQ * DIM],  g_ql[(size_t)SQ * DIM];
__device__ __nv_bfloat16 g_kh[(size_t)SQ * KVD],  g_kl[(size_t)SQ * KVD];
__device__ __nv_bfloat16 g_vth[(size_t)KVD * SQ], g_vtl[(size_t)KVD * SQ];
__device__ __nv_bfloat16 g_ah[(size_t)SQ * DIM],  g_al[(size_t)SQ * DIM];
__device__ __nv_bfloat16 g_ph[(size_t)NH * SQ * SQ], g_pl[(size_t)NH * SQ * SQ];
__device__ __nv_bfloat16 g_wqh[(size_t)DIM * DIM], g_wql[(size_t)DIM * DIM];
__device__ __nv_bfloat16 g_wkh[(size_t)KVD * DIM], g_wkl[(size_t)KVD * DIM];
__device__ __nv_bfloat16 g_wvh[(size_t)KVD * DIM], g_wvl[(size_t)KVD * DIM];
__device__ __nv_bfloat16 g_woh[(size_t)DIM * DIM], g_wol[(size_t)DIM * DIM];

// ---------------- helpers ----------------
__device__ __forceinline__ uint32_t smem_u32(const void* p) {
    uint32_t a;
    asm("{ .reg .u64 t; cvta.to.shared.u64 t, %1; cvt.u32.u64 %0, t; }" : "=r"(a) : "l"(p));
    return a;
}
__device__ __forceinline__ void ldm4(uint32_t* r, uint32_t addr) {
    asm volatile("ldmatrix.sync.aligned.m8n8.x4.shared.b16 {%0,%1,%2,%3}, [%4];"
                 : "=r"(r[0]), "=r"(r[1]), "=r"(r[2]), "=r"(r[3]) : "r"(addr));
}
__device__ __forceinline__ void mma16816(float* c, const uint32_t* a, uint32_t b0, uint32_t b1) {
    asm volatile(
        "mma.sync.aligned.m16n8k16.row.col.f32.bf16.bf16.f32 "
        "{%0,%1,%2,%3}, {%4,%5,%6,%7}, {%8,%9}, {%0,%1,%2,%3};"
        : "+f"(c[0]), "+f"(c[1]), "+f"(c[2]), "+f"(c[3])
        : "r"(a[0]), "r"(a[1]), "r"(a[2]), "r"(a[3]), "r"(b0), "r"(b1));
}

// ---------------------------------------------------------------------------
// Split-bf16 tensor-core GEMM via mma.sync: C[M,N] fp32 = (Ah+Al)*(Bh+Bl)^T
// (3 terms: Ah*Bh + Ah*Bl + Al*Bh). A:[M,K] row-major, B:[N,K] row-major.
// 128x128 CTA tile, 8 warps (4m x 2n), warp tile 32x64, BK=32, double-buffered.
// flags bit0: causal tile skip; bit1: PV causal K truncation (nk=4*by+4)
// ---------------------------------------------------------------------------
#define PITCHB 80                    // smem row pitch in bytes (32 bf16 + 8 pad)
#define OPB    (128 * PITCHB)        // bytes per operand tile = 10240
#define BUFB   (4 * OPB)             // 4 operands per buffer = 40960
#define GEMM_SMEM (2 * BUFB)         // 81920

__global__ __launch_bounds__(256) void gemm_tc(
    const __nv_bfloat16* __restrict__ Ah, const __nv_bfloat16* __restrict__ Al, int lda, long long aZ,
    const __nv_bfloat16* __restrict__ Bh, const __nv_bfloat16* __restrict__ Bl, int ldb, long long bZ, int bzs,
    float* __restrict__ C, int ldc, long long cZ, int nk, int flags)
{
    if ((flags & 1) && blockIdx.x > blockIdx.y) return;
    if (flags & 2) nk = 4 * blockIdx.y + 4;
    extern __shared__ char smem[];
    const uint32_t sb = smem_u32(smem);
    const int tid = threadIdx.x, lane = tid & 31, wid = tid >> 5;
    const int wm = wid & 3, wn = wid >> 2;
    const int z = blockIdx.z;
    Ah += (long long)z * aZ;  Al += (long long)z * aZ;
    { long long bo = (long long)(z >> bzs) * bZ; Bh += bo; Bl += bo; }
    C += (long long)z * cZ;
    const int m0 = blockIdx.y * 128, n0 = blockIdx.x * 128;

    float acc[2][8][4];
    #pragma unroll
    for (int i = 0; i < 2; i++)
        #pragma unroll
        for (int j = 0; j < 8; j++)
            #pragma unroll
            for (int c = 0; c < 4; c++) acc[i][j][c] = 0.f;

    // loader index: linear 0..511 -> row=linear>>2, c4=linear&3 (uint4 = 8 bf16)
    const int lrow = tid >> 1;                 // not used; keep mapping below
    (void)lrow;
    uint4 pre[4][2];

    const __nv_bfloat16* OPS[4] = {Ah, Al, Bh, Bl};

    #define LOAD_CHUNK(KC)                                                        \
        {                                                                         \
            const long long ko = (long long)(KC) * 32;                            \
            _Pragma("unroll")                                                     \
            for (int o = 0; o < 4; o++) {                                         \
                const __nv_bfloat16* P = OPS[o];                                  \
                const int ld_ = (o < 2) ? lda : ldb;                              \
                const int rb  = (o < 2) ? m0 : n0;                                \
                _Pragma("unroll")                                                 \
                for (int j = 0; j < 2; j++) {                                     \
                    int linear = tid + j * 256;                                   \
                    int row = linear >> 2, c4 = linear & 3;                       \
                    pre[o][j] = *(const uint4*)(P + (size_t)(rb + row) * ld_ + ko + c4 * 8); \
                }                                                                 \
            }                                                                     \
        }

    #define STORE_CHUNK(BUF)                                                      \
        {                                                                         \
            _Pragma("unroll")                                                     \
            for (int o = 0; o < 4; o++) {                                         \
                _Pragma("unroll")                                                 \
                for (int j = 0; j < 2; j++) {                                     \
                    int linear = tid + j * 256;                                   \
                    int row = linear >> 2, c4 = linear & 3;                       \
                    *(uint4*)(smem + (BUF) * BUFB + o * OPB + row * PITCHB + c4 * 16) = pre[o][j]; \
                }                                                                 \
            }                                                                     \
        }

    LOAD_CHUNK(0);
    STORE_CHUNK(0);
    __syncthreads();

    for (int kc = 0; kc < nk; kc++) {
        const int cur = kc & 1;
        if (kc + 1 < nk) LOAD_CHUNK(kc + 1);

        // ---- compute on buffer cur ----
        const uint32_t base = sb + cur * BUFB;
        const uint32_t aHb = base + (uint32_t)((wm * 32 + (lane & 15)) * PITCHB + (lane >> 4) * 16);
        const uint32_t aLb = aHb + OPB;
        const uint32_t bRow = (uint32_t)(wn * 64 + (lane & 7) + ((lane >> 4) * 8));
        const uint32_t bHb = base + 2 * OPB + bRow * PITCHB + (((lane >> 3) & 1) * 16);
        const uint32_t bLb = bHb + OPB;

        #pragma unroll
        for (int ks = 0; ks < 2; ks++) {
            const uint32_t ko = ks * 32;
            uint32_t aH[2][4], aL[2][4], bH[4][4], bL[4][4];
            #pragma unroll
            for (int mt = 0; mt < 2; mt++) {
                ldm4(aH[mt], aHb + mt * (16 * PITCHB) + ko);
                ldm4(aL[mt], aLb + mt * (16 * PITCHB) + ko);
            }
            #pragma unroll
            for (int np = 0; np < 4; np++) {
                ldm4(bH[np], bHb + np * (16 * PITCHB) + ko);
                ldm4(bL[np], bLb + np * (16 * PITCHB) + ko);
            }
            #pragma unroll
            for (int mt = 0; mt < 2; mt++)
                #pragma unroll
                for (int np = 0; np < 4; np++) {
                    mma16816(acc[mt][2 * np],     aH[mt], bH[np][0], bH[np][1]);
                    mma16816(acc[mt][2 * np + 1], aH[mt], bH[np][2], bH[np][3]);
                    mma16816(acc[mt][2 * np],     aH[mt], bL[np][0], bL[np][1]);
                    mma16816(acc[mt][2 * np + 1], aH[mt], bL[np][2], bL[np][3]);
                    mma16816(acc[mt][2 * np],     aL[mt], bH[np][0], bH[np][1]);
                    mma16816(acc[mt][2 * np + 1], aL[mt], bH[np][2], bH[np][3]);
                }
        }

        if (kc + 1 < nk) {
            STORE_CHUNK((kc + 1) & 1);
            __syncthreads();
        }
    }

    // ---- epilogue ----
    #pragma unroll
    for (int mt = 0; mt < 2; mt++)
        #pragma unroll
        for (int nt = 0; nt < 8; nt++) {
            const int r0 = m0 + wm * 32 + mt * 16 + (lane >> 2);
            const int cc = n0 + wn * 64 + nt * 8 + (lane & 3) * 2;
            *(float2*)&C[(size_t)r0 * ldc + cc]       = make_float2(acc[mt][nt][0], acc[mt][nt][1]);
            *(float2*)&C[(size_t)(r0 + 8) * ldc + cc] = make_float2(acc[mt][nt][2], acc[mt][nt][3]);
        }
    #undef LOAD_CHUNK
    #undef STORE_CHUNK
}

// ---------------- small kernels ----------------
__global__ void split_kernel(const float* __restrict__ in, __nv_bfloat16* __restrict__ hi,
                             __nv_bfloat16* __restrict__ lo, size_t n)
{
    size_t i = (size_t)blockIdx.x * blockDim.x + threadIdx.x;
    if (i >= n) return;
    float v = in[i];
    __nv_bfloat16 h = __float2bfloat16(v);
    hi[i] = h;
    lo[i] = __float2bfloat16(v - __bfloat162float(h));
}

__global__ void transpose_split(const float* __restrict__ in, __nv_bfloat16* __restrict__ hi,
                                __nv_bfloat16* __restrict__ lo, int K, int N)
{
    __shared__ float t[32][33];
    int k0 = blockIdx.y * 32, n0 = blockIdx.x * 32;
    int tx = threadIdx.x, ty = threadIdx.y;     // (32,8)
    #pragma unroll
    for (int i = 0; i < 4; i++)
        t[ty + i * 8][tx] = in[(size_t)(k0 + ty + i * 8) * N + n0 + tx];
    __syncthreads();
    #pragma unroll
    for (int i = 0; i < 4; i++) {
        float v = t[tx][ty + i * 8];
        __nv_bfloat16 h = __float2bfloat16(v);
        size_t o = (size_t)(n0 + ty + i * 8) * K + k0 + tx;
        hi[o] = h;
        lo[o] = __float2bfloat16(v - __bfloat162float(h));
    }
}

__global__ void rope_kernel(float* __restrict__ t,
                            const float* __restrict__ cosT,
                            const float* __restrict__ sinT,
                            int nheads, int ld)
{
    int i = blockIdx.x * blockDim.x + threadIdx.x;
    int total = SQ * nheads * (HD / 2);
    if (i >= total) return;
    int p = i & 63;
    int rest = i >> 6;
    int h = rest % nheads;
    int s = rest / nheads;
    float c  = cosT[s * 64 + p];
    float sn = sinT[s * 64 + p];
    float* base = t + (size_t)s * ld + h * HD + 2 * p;
    float x1 = base[0], x2 = base[1];
    base[0] = x1 * c - x2 * sn;
    base[1] = x1 * sn + x2 * c;
}

__global__ __launch_bounds__(256) void softmax_kernel()
{
    const int s = blockIdx.x;
    const int h = blockIdx.y;
    const float* row = g_sc + ((size_t)h * SQ + s) * SQ;
    __nv_bfloat16* ph = g_ph + ((size_t)h * SQ + s) * SQ;
    __nv_bfloat16* pl = g_pl + ((size_t)h * SQ + s) * SQ;
    const int L = s + 1;
    const int lim = ((s >> 7) + 1) << 7;
    const float scale = 0.08838834764831845f;   // 1/sqrt(128)
    __shared__ float red[256];
    const int t0 = threadIdx.x;

    float m = -1e30f;
    for (int t = t0; t < L; t += 256) m = fmaxf(m, row[t]);
    red[t0] = m;
    __syncthreads();
    for (int o = 128; o > 0; o >>= 1) {
        if (t0 < o) red[t0] = fmaxf(red[t0], red[t0 + o]);
        __syncthreads();
    }
    m = red[0] * scale;
    __syncthreads();

    float sum = 0.f;
    for (int t = t0; t < L; t += 256) sum += __expf(row[t] * scale - m);
    red[t0] = sum;
    __syncthreads();
    for (int o = 128; o > 0; o >>= 1) {
        if (t0 < o) red[t0] += red[t0 + o];
        __syncthreads();
    }
    const float inv = 1.f / red[0];

    for (int t = t0; t < L; t += 256) {
        float p = __expf(row[t] * scale - m) * inv;
        __nv_bfloat16 hh = __float2bfloat16(p);
        ph[t] = hh;
        pl[t] = __float2bfloat16(p - __bfloat162float(hh));
    }
    for (int t = L + t0; t < lim; t += 256) {
        ph[t] = __float2bfloat16(0.f);
        pl[t] = __float2bfloat16(0.f);
    }
}

// ---------------------------------------------------------------------------
// Inputs: 0:x 1:start_pos 2:freqs_cos 3:freqs_sin 4:mask 5:wq 6:wk 7:wv 8:wo
// ---------------------------------------------------------------------------
extern "C" void kernel_launch(void* const* d_in, const int* in_sizes, int n_in,
                              void* d_out, int out_size)
{
    const float* x    = (const float*)d_in[0];
    const float* fcos = (const float*)d_in[2];
    const float* fsin = (const float*)d_in[3];
    const float* wq   = (const float*)d_in[5];
    const float* wk   = (const float*)d_in[6];
    const float* wv   = (const float*)d_in[7];
    const float* wo   = (const float*)d_in[8];
    float* out = (float*)d_out;

    float *q, *k, *v, *at, *sc;
    cudaGetSymbolAddress((void**)&q,  g_q);
    cudaGetSymbolAddress((void**)&k,  g_k);
    cudaGetSymbolAddress((void**)&v,  g_v);
    cudaGetSymbolAddress((void**)&at, g_attn);
    cudaGetSymbolAddress((void**)&sc, g_sc);
    __nv_bfloat16 *xh, *xl, *qh, *ql, *kh, *kl, *vth, *vtl, *ah, *al, *ph, *pl;
    __nv_bfloat16 *wqh, *wql, *wkh, *wkl, *wvh, *wvl, *woh, *wol;
    cudaGetSymbolAddress((void**)&xh,  g_xh);  cudaGetSymbolAddress((void**)&xl,  g_xl);
    cudaGetSymbolAddress((void**)&qh,  g_qh);  cudaGetSymbolAddress((void**)&ql,  g_ql);
    cudaGetSymbolAddress((void**)&kh,  g_kh);  cudaGetSymbolAddress((void**)&kl,  g_kl);
    cudaGetSymbolAddress((void**)&vth, g_vth); cudaGetSymbolAddress((void**)&vtl, g_vtl);
    cudaGetSymbolAddress((void**)&ah,  g_ah);  cudaGetSymbolAddress((void**)&al,  g_al);
    cudaGetSymbolAddress((void**)&ph,  g_ph);  cudaGetSymbolAddress((void**)&pl,  g_pl);
    cudaGetSymbolAddress((void**)&wqh, g_wqh); cudaGetSymbolAddress((void**)&wql, g_wql);
    cudaGetSymbolAddress((void**)&wkh, g_wkh); cudaGetSymbolAddress((void**)&wkl, g_wkl);
    cudaGetSymbolAddress((void**)&wvh, g_wvh); cudaGetSymbolAddress((void**)&wvl, g_wvl);
    cudaGetSymbolAddress((void**)&woh, g_woh); cudaGetSymbolAddress((void**)&wol, g_wol);

    cudaFuncSetAttribute(gemm_tc, cudaFuncAttributeMaxDynamicSharedMemorySize, GEMM_SMEM);

    const dim3 tb(32, 8);

    // x -> split bf16; weights -> transposed split ([N,K] K-major)
    split_kernel<<<(unsigned)(((size_t)SQ * DIM + 255) / 256), 256>>>(x, xh, xl, (size_t)SQ * DIM);
    transpose_split<<<dim3(DIM / 32, DIM / 32), tb>>>(wq, wqh, wql, DIM, DIM);
    transpose_split<<<dim3(KVD / 32, DIM / 32), tb>>>(wk, wkh, wkl, DIM, KVD);
    transpose_split<<<dim3(KVD / 32, DIM / 32), tb>>>(wv, wvh, wvl, DIM, KVD);
    transpose_split<<<dim3(DIM / 32, DIM / 32), tb>>>(wo, woh, wol, DIM, DIM);

    // QKV projections (tensor cores, nk = K/32)
    gemm_tc<<<dim3(DIM / 128, SQ / 128), 256, GEMM_SMEM>>>(xh, xl, DIM, 0, wqh, wql, DIM, 0, 0, q, DIM, 0, DIM / 32, 0);
    gemm_tc<<<dim3(KVD / 128, SQ / 128), 256, GEMM_SMEM>>>(xh, xl, DIM, 0, wkh, wkl, DIM, 0, 0, k, KVD, 0, DIM / 32, 0);
    gemm_tc<<<dim3(KVD / 128, SQ / 128), 256, GEMM_SMEM>>>(xh, xl, DIM, 0, wvh, wvl, DIM, 0, 0, v, KVD, 0, DIM / 32, 0);

    // RoPE (fp32)
    rope_kernel<<<(SQ * NH * 64 + 255) / 256, 256>>>(q, fcos, fsin, NH, DIM);
    rope_kernel<<<(SQ * NKV * 64 + 255) / 256, 256>>>(k, fcos, fsin, NKV, KVD);

    // q,k -> split; v -> transposed split (per-head V^T)
    split_kernel<<<(unsigned)(((size_t)SQ * DIM + 255) / 256), 256>>>(q, qh, ql, (size_t)SQ * DIM);
    split_kernel<<<(unsigned)(((size_t)SQ * KVD + 255) / 256), 256>>>(k, kh, kl, (size_t)SQ * KVD);
    transpose_split<<<dim3(KVD / 32, SQ / 32), tb>>>(v, vth, vtl, SQ, KVD);

    // QK^T (causal tile skip): nk = HD/32 = 4
    gemm_tc<<<dim3(SQ / 128, SQ / 128, NH), 256, GEMM_SMEM>>>(
        qh, ql, DIM, 128, kh, kl, KVD, 128, 2, sc, SQ, (long long)SQ * SQ, HD / 32, 1);

    // softmax -> split probs
    softmax_kernel<<<dim3(SQ, NH), 256>>>();

    // PV: nk truncated causally (flags bit1)
    gemm_tc<<<dim3(1, SQ / 128, NH), 256, GEMM_SMEM>>>(
        ph, pl, SQ, (long long)SQ * SQ, vth, vtl, SQ, (long long)HD * SQ, 2, at, DIM, HD, 0, 2);

    // attn -> split; output projection
    split_kernel<<<(unsigned)(((size_t)SQ * DIM + 255) / 256), 256>>>(at, ah, al, (size_t)SQ * DIM);
    gemm_tc<<<dim3(DIM / 128, SQ / 128), 256, GEMM_SMEM>>>(ah, al, DIM, 0, woh, wol, DIM, 0, 0, out, DIM, 0, DIM / 32, 0);
}